// round 16
// baseline (speedup 1.0000x reference)
#include <cuda_runtime.h>
#include <cuda_fp16.h>
#include <cstddef>
#include <cstdint>

// Problem constants
#define NB    16
#define NS    1024
#define ND    384      // H * HD
#define NH    6
#define NHD   64
#define NK    9
#define NKH   54       // K * H
#define NKHP  64       // padded logits width
#define NOUT  384
#define NPAD  4        // K/2

// Fused kernel tiling
#define TSR      64    // seq rows per block
#define NTH      1024  // 32 warps
#define AST      392   // fp16 plane row stride (halfs) — conflict-free LDSM
#define VR       40    // v rows staged per conv half-pass (32 + 8 halo)

#define NKSTEP   24
#define NJT      6     // n8 tiles per warp in P5
#define NCB      8     // col blocks of 48

// Wp pack (fp16): [t(24)][cb(8)][lane(32)][j(6)][p(2)]
#define BPACK_WORDS (NKSTEP * NCB * 32 * NJT * 2)      // 73728
// Wk pack (fp16): [t(24)][lane(32)][j(8)][p(2)]
#define WKPACK_WORDS (NKSTEP * 32 * 8 * 2)             // 12288

// ---------------- fp16 mma ----------------
__device__ __forceinline__ void mma_f16(float* c,
                                        unsigned a0, unsigned a1,
                                        unsigned a2, unsigned a3,
                                        unsigned b0, unsigned b1) {
    asm volatile(
        "mma.sync.aligned.m16n8k16.row.col.f32.f16.f16.f32 "
        "{%0,%1,%2,%3}, {%4,%5,%6,%7}, {%8,%9}, {%0,%1,%2,%3};\n"
        : "+f"(c[0]), "+f"(c[1]), "+f"(c[2]), "+f"(c[3])
        : "r"(a0), "r"(a1), "r"(a2), "r"(a3), "r"(b0), "r"(b1));
}

__device__ __forceinline__ void ldsm_x4(unsigned& r0, unsigned& r1,
                                        unsigned& r2, unsigned& r3,
                                        unsigned addr) {
    asm volatile(
        "ldmatrix.sync.aligned.m8n8.x4.shared.b16 {%0,%1,%2,%3}, [%4];"
        : "=r"(r0), "=r"(r1), "=r"(r2), "=r"(r3) : "r"(addr));
}

__device__ __forceinline__ unsigned smem_u32(const void* p) {
    unsigned a;
    asm("{ .reg .u64 t; cvta.to.shared.u64 t, %1; cvt.u32.u64 %0, t; }"
        : "=r"(a) : "l"(p));
    return a;
}

__device__ __forceinline__ void cp_async16(unsigned dst, const void* src, int src_bytes) {
    asm volatile("cp.async.cg.shared.global [%0], [%1], 16, %2;\n"
                 :: "r"(dst), "l"(src), "r"(src_bytes));
}
__device__ __forceinline__ void cp_async_commit() {
    asm volatile("cp.async.commit_group;\n" ::: "memory");
}
__device__ __forceinline__ void cp_async_wait0() {
    asm volatile("cp.async.wait_group 0;\n" ::: "memory");
}

__device__ unsigned int g_Bpack[BPACK_WORDS];
__device__ unsigned int g_WkPack[WKPACK_WORDS];

__global__ void prep_kernel(const float* __restrict__ Wp,
                            const float* __restrict__ Wk) {
    int i = blockIdx.x * blockDim.x + threadIdx.x;
    if (i < BPACK_WORDS) {
        int p  = i & 1;
        int j  = (i >> 1) % NJT;
        int l  = (i / (NJT * 2)) & 31;
        int cb = (i / (NJT * 2 * 32)) % NCB;
        int t  =  i / (NJT * 2 * 32 * NCB);
        int o  = cb * 48 + j * 8 + (l >> 2);
        int k0 = t * 16 + (l & 3) * 2 + (p ? 8 : 0);
        __half2 h = __floats2half2_rn(Wp[o * ND + k0], Wp[o * ND + k0 + 1]);
        g_Bpack[i] = *reinterpret_cast<unsigned*>(&h);
    }
    if (i < WKPACK_WORDS) {
        int p  = i & 1;
        int j  = (i >> 1) & 7;
        int l  = (i >> 4) & 31;
        int t  =  i >> 9;
        int o  = j * 8 + (l >> 2);
        int k0 = t * 16 + (l & 3) * 2 + (p ? 8 : 0);
        float x = (o < NKH) ? Wk[o * ND + k0]     : 0.f;
        float y = (o < NKH) ? Wk[o * ND + k0 + 1] : 0.f;
        __half2 h = __floats2half2_rn(x, y);
        g_WkPack[i] = *reinterpret_cast<unsigned*>(&h);
    }
}

// ============================================================================
// Fused kernel: one block = (batch, 64 seq rows), 1024 threads, <=64 regs
// smem (floats, total 32000 = 128000 B):
//   sA  [0, 12544):         64 x 392 fp16 halfs (q*ks, then conv out)
//   sV  [12544, 27904):     40 x 384 fp32
//   sL  [27904, 32000):     64 x 64 fp32
// ============================================================================
#define SMEM_FLOATS 32000

__global__ __launch_bounds__(NTH, 1) void sdca_fused(
    const float* __restrict__ q,
    const float* __restrict__ ks,
    const float* __restrict__ v,
    const float* __restrict__ bk,
    const float* __restrict__ bp,
    float* __restrict__ out)
{
    extern __shared__ float smem[];
    __half* sA = (__half*)smem;                  // 64 x AST halfs
    float* sV = smem + 12544;
    float* sL = smem + 27904;

    const int tid  = threadIdx.x;
    const int lane = tid & 31;
    const int wrp  = tid >> 5;                    // 0..31
    const int b    = blockIdx.x / (NS / TSR);
    const int s0   = (blockIdx.x % (NS / TSR)) * TSR;

    const int lm_row = lane & 15;
    const int lm_col = (lane >> 4) * 8;

    const float* vb = v + (size_t)b * NS * ND;

    // ---- P0: cp.async prefetch of conv pass-1 v window (rows s0-4 .. s0+35) ----
    {
        const unsigned sv_base = smem_u32(sV);
        #pragma unroll
        for (int i = tid; i < VR * (ND / 4); i += NTH) {
            int rr = i / (ND / 4);
            int cc = i % (ND / 4);
            int gr = s0 - NPAD + rr;
            int ok = (gr >= 0 && gr < NS) ? 16 : 0;
            const float4* src = (const float4*)(vb + (size_t)max(gr, 0) * ND) + cc;
            cp_async16(sv_base + i * 16, src, ok);
        }
        cp_async_commit();
    }

    // ---- P1: sA = fp16(q * ks) ----
    {
        const float4* qb = (const float4*)(q  + ((size_t)b * NS + s0) * ND);
        const float4* kb = (const float4*)(ks + ((size_t)b * NS + s0) * ND);
        #pragma unroll
        for (int i = tid; i < TSR * (ND / 4); i += NTH) {
            int r  = i / (ND / 4);
            int c4 = (i % (ND / 4)) * 4;
            float4 qq = qb[i], kk = kb[i];
            __half2 h01 = __floats2half2_rn(qq.x * kk.x, qq.y * kk.y);
            __half2 h23 = __floats2half2_rn(qq.z * kk.z, qq.w * kk.w);
            uint2 wh;
            wh.x = *reinterpret_cast<unsigned*>(&h01);
            wh.y = *reinterpret_cast<unsigned*>(&h23);
            *(uint2*)&sA[r * AST + c4] = wh;
        }
    }
    __syncthreads();

    // ---- P2: logits[64 x 64] via fp16 mma; warp = (m-quarter, n8 tile) ----
    {
        const int wm = wrp & 3;                   // 16-row group
        const int wn = wrp >> 2;                  // n8 tile 0..7
        const int rq = lane >> 2;
        const int kc = (lane & 3) * 2;
        float acc[4] = {0.f, 0.f, 0.f, 0.f};

        unsigned a_base = smem_u32(sA + (size_t)(wm * 16 + lm_row) * AST + lm_col);

        for (int t = 0; t < NKSTEP; t++) {
            uint2 B = *(const uint2*)(g_WkPack + (((size_t)(t * 32 + lane)) * 8 + wn) * 2);
            unsigned a0, a1, a2, a3;
            ldsm_x4(a0, a1, a2, a3, a_base + t * 32);
            mma_f16(acc, a0, a1, a2, a3, B.x, B.y);
        }

        int oc = wn * 8 + kc;
        float bk0 = (oc < NKH)     ? bk[oc]     : 0.f;
        float bk1 = (oc + 1 < NKH) ? bk[oc + 1] : 0.f;
        int r = wm * 16 + rq;
        sL[r * NKHP + oc]           = acc[0] + bk0;
        sL[r * NKHP + oc + 1]       = acc[1] + bk1;
        sL[(r + 8) * NKHP + oc]     = acc[2] + bk0;
        sL[(r + 8) * NKHP + oc + 1] = acc[3] + bk1;
    }
    __syncthreads();

    // ---- P3: softmax over K=9 taps per (row, head) ----
    if (tid < TSR * NH) {
        int r = tid / NH, h = tid % NH;
        float* p = sL + r * NKHP + h * NK;
        float m = p[0];
        #pragma unroll
        for (int k = 1; k < NK; k++) m = fmaxf(m, p[k]);
        float e[NK], ssum = 0.f;
        #pragma unroll
        for (int k = 0; k < NK; k++) { e[k] = __expf(p[k] - m); ssum += e[k]; }
        float inv = 1.0f / ssum;
        #pragma unroll
        for (int k = 0; k < NK; k++) p[k] = e[k] * inv;
    }
    cp_async_wait0();           // pass-1 v window resident
    __syncthreads();

    // ---- P4: conv, warp-unit = (head, 8-row block), sliding v window ----
    // 24 units per half; 32 warps: it=0 covers 24 (wrp<24), it=1 none needed.
    {
        #pragma unroll
        for (int half = 0; half < 2; half++) {
            if (half == 1) {
                __syncthreads();
                int gbase = s0 - NPAD + 32;
                float4* sv4 = (float4*)sV;
                for (int i = tid; i < VR * ND / 4; i += NTH) {
                    int rr = i / (ND / 4);
                    int gr = gbase + rr;
                    float4 val = make_float4(0.f, 0.f, 0.f, 0.f);
                    if (gr >= 0 && gr < NS)
                        val = ((const float4*)(vb + (size_t)gr * ND))[i % (ND / 4)];
                    sv4[i] = val;
                }
                __syncthreads();
            }

            if (wrp < 24) {
                int h  = wrp % NH;
                int rb = wrp / NH;                // 0..3
                int c0 = h * NHD + lane * 2;
                int r0 = rb * 8;

                float2 w[16];
                #pragma unroll
                for (int j = 0; j < 16; j++)
                    w[j] = *(const float2*)&sV[(r0 + j) * ND + c0];

                #pragma unroll
                for (int i = 0; i < 8; i++) {
                    int r = half * 32 + r0 + i;
                    const float* dkp = sL + r * NKHP + h * NK;
                    float a0 = 0.f, a1 = 0.f;
                    #pragma unroll
                    for (int k = 0; k < NK; k++) {
                        float dk = dkp[k];
                        a0 = fmaf(dk, w[i + k].x, a0);
                        a1 = fmaf(dk, w[i + k].y, a1);
                    }
                    __half2 hv = __floats2half2_rn(a0, a1);
                    *(unsigned*)&sA[r * AST + c0] = *reinterpret_cast<unsigned*>(&hv);
                }
            }
        }
        __syncthreads();
    }

    // ---- P5: out[64 x 384] = A @ Wp^T + bp; warp = 16 rows x 48 cols ----
    {
        const int warp_m = wrp & 3;               // 16-row group 0..3
        const int warp_n = wrp >> 2;              // 48-col block 0..7
        const int rb     = warp_m * 16;
        const int rq     = lane >> 2;
        const int kc     = (lane & 3) * 2;

        float acc[NJT][4];
        #pragma unroll
        for (int j = 0; j < NJT; j++)
            #pragma unroll
            for (int p = 0; p < 4; p++) acc[j][p] = 0.f;

        unsigned a_base = smem_u32(sA + (size_t)(rb + lm_row) * AST + lm_col);

        for (int t = 0; t < NKSTEP; t++) {
            unsigned a0, a1, a2, a3;
            ldsm_x4(a0, a1, a2, a3, a_base + t * 32);

            const uint4* bptr =
                (const uint4*)(g_Bpack + ((size_t)((t * NCB + warp_n) * 32 + lane)) * (NJT * 2));
            uint4 B0 = bptr[0], B1 = bptr[1], B2 = bptr[2];
            mma_f16(acc[0], a0, a1, a2, a3, B0.x, B0.y);
            mma_f16(acc[1], a0, a1, a2, a3, B0.z, B0.w);
            mma_f16(acc[2], a0, a1, a2, a3, B1.x, B1.y);
            mma_f16(acc[3], a0, a1, a2, a3, B1.z, B1.w);
            mma_f16(acc[4], a0, a1, a2, a3, B2.x, B2.y);
            mma_f16(acc[5], a0, a1, a2, a3, B2.z, B2.w);
        }

        const int nbase = warp_n * 48;
        float* ob = out + ((size_t)b * NS + s0) * NOUT;
        #pragma unroll
        for (int j = 0; j < NJT; j++) {
            int c = nbase + j * 8 + kc;
            float2 bb = *(const float2*)&bp[c];
            size_t R = (size_t)(rb + rq);
            float2 lo = make_float2(acc[j][0] + bb.x, acc[j][1] + bb.y);
            float2 hi = make_float2(acc[j][2] + bb.x, acc[j][3] + bb.y);
            *(float2*)&ob[R * NOUT + c]       = lo;
            *(float2*)&ob[(R + 8) * NOUT + c] = hi;
        }
    }
}

extern "C" void kernel_launch(void* const* d_in, const int* in_sizes, int n_in,
                              void* d_out, int out_size) {
    const float* q  = (const float*)d_in[0];
    const float* ks = (const float*)d_in[1];
    const float* v  = (const float*)d_in[2];
    const float* Wk = (const float*)d_in[3];
    const float* bk = (const float*)d_in[4];
    const float* Wp = (const float*)d_in[5];
    const float* bp = (const float*)d_in[6];
    float* out = (float*)d_out;

    (void)in_sizes; (void)n_in; (void)out_size;

    prep_kernel<<<(BPACK_WORDS + 255) / 256, 256>>>(Wp, Wk);

    const int smem_bytes = SMEM_FLOATS * (int)sizeof(float);  // 128000
    cudaFuncSetAttribute(sdca_fused, cudaFuncAttributeMaxDynamicSharedMemorySize, smem_bytes);
    sdca_fused<<<NB * (NS / TSR), NTH, smem_bytes>>>(q, ks, v, bk, bp, out);
}

// round 17
// speedup vs baseline: 1.2675x; 1.2675x over previous
#include <cuda_runtime.h>
#include <cuda_fp16.h>
#include <cstddef>
#include <cstdint>

// Problem constants
#define NB    16
#define NS    1024
#define ND    384      // H * HD
#define NH    6
#define NHD   64
#define NK    9
#define NKH   54       // K * H
#define NKHP  64       // padded logits width
#define NOUT  384
#define NPAD  4        // K/2

// Fused kernel tiling (R15 base)
#define TSR      64    // seq rows per block
#define NTH      512
#define AST      392   // fp16 plane row stride (halfs) — conflict-free LDSM
#define VR       40    // v rows per conv window (32 + 8 halo)

#define NKSTEP   24
#define NJT      6     // n8 tiles per warp in P5
#define NCB      8     // col blocks of 48

// Wp pack (fp16): [t(24)][cb(8)][lane(32)][j(6)][p(2)]
#define BPACK_WORDS (NKSTEP * NCB * 32 * NJT * 2)      // 73728
// Wk pack (fp16): [t(24)][lane(32)][j(8)][p(2)]
#define WKPACK_WORDS (NKSTEP * 32 * 8 * 2)             // 12288

// ---------------- fp16 mma ----------------
__device__ __forceinline__ void mma_f16(float* c,
                                        unsigned a0, unsigned a1,
                                        unsigned a2, unsigned a3,
                                        unsigned b0, unsigned b1) {
    asm volatile(
        "mma.sync.aligned.m16n8k16.row.col.f32.f16.f16.f32 "
        "{%0,%1,%2,%3}, {%4,%5,%6,%7}, {%8,%9}, {%0,%1,%2,%3};\n"
        : "+f"(c[0]), "+f"(c[1]), "+f"(c[2]), "+f"(c[3])
        : "r"(a0), "r"(a1), "r"(a2), "r"(a3), "r"(b0), "r"(b1));
}

__device__ __forceinline__ void ldsm_x4(unsigned& r0, unsigned& r1,
                                        unsigned& r2, unsigned& r3,
                                        unsigned addr) {
    asm volatile(
        "ldmatrix.sync.aligned.m8n8.x4.shared.b16 {%0,%1,%2,%3}, [%4];"
        : "=r"(r0), "=r"(r1), "=r"(r2), "=r"(r3) : "r"(addr));
}

__device__ __forceinline__ unsigned smem_u32(const void* p) {
    unsigned a;
    asm("{ .reg .u64 t; cvta.to.shared.u64 t, %1; cvt.u32.u64 %0, t; }"
        : "=r"(a) : "l"(p));
    return a;
}

__device__ __forceinline__ void cp_async16(unsigned dst, const void* src, int src_bytes) {
    asm volatile("cp.async.cg.shared.global [%0], [%1], 16, %2;\n"
                 :: "r"(dst), "l"(src), "r"(src_bytes));
}
__device__ __forceinline__ void cp_async_commit() {
    asm volatile("cp.async.commit_group;\n" ::: "memory");
}
template <int N>
__device__ __forceinline__ void cp_async_wait() {
    asm volatile("cp.async.wait_group %0;\n" :: "n"(N) : "memory");
}

__device__ unsigned int g_Bpack[BPACK_WORDS];
__device__ unsigned int g_WkPack[WKPACK_WORDS];

__global__ void prep_kernel(const float* __restrict__ Wp,
                            const float* __restrict__ Wk) {
    int i = blockIdx.x * blockDim.x + threadIdx.x;
    if (i < BPACK_WORDS) {
        int p  = i & 1;
        int j  = (i >> 1) % NJT;
        int l  = (i / (NJT * 2)) & 31;
        int cb = (i / (NJT * 2 * 32)) % NCB;
        int t  =  i / (NJT * 2 * 32 * NCB);
        int o  = cb * 48 + j * 8 + (l >> 2);
        int k0 = t * 16 + (l & 3) * 2 + (p ? 8 : 0);
        __half2 h = __floats2half2_rn(Wp[o * ND + k0], Wp[o * ND + k0 + 1]);
        g_Bpack[i] = *reinterpret_cast<unsigned*>(&h);
    }
    if (i < WKPACK_WORDS) {
        int p  = i & 1;
        int j  = (i >> 1) & 7;
        int l  = (i >> 4) & 31;
        int t  =  i >> 9;
        int o  = j * 8 + (l >> 2);
        int k0 = t * 16 + (l & 3) * 2 + (p ? 8 : 0);
        float x = (o < NKH) ? Wk[o * ND + k0]     : 0.f;
        float y = (o < NKH) ? Wk[o * ND + k0 + 1] : 0.f;
        __half2 h = __floats2half2_rn(x, y);
        g_WkPack[i] = *reinterpret_cast<unsigned*>(&h);
    }
}

// ============================================================================
// Fused kernel: one block = (batch, 64 seq rows), 512 threads
// smem (floats, total 47360 = 189440 B):
//   sA  [0, 12544):         64 x 392 fp16 halfs (q*ks, then conv out)
//   sV0 [12544, 27904):     40 x 384 fp32  (conv pass-1 window)
//   sV1 [27904, 43264):     40 x 384 fp32  (conv pass-2 window)
//   sL  [43264, 47360):     64 x 64 fp32
// ============================================================================
#define SMEM_FLOATS 47360

__global__ __launch_bounds__(NTH, 1) void sdca_fused(
    const float* __restrict__ q,
    const float* __restrict__ ks,
    const float* __restrict__ v,
    const float* __restrict__ bk,
    const float* __restrict__ bp,
    float* __restrict__ out)
{
    extern __shared__ float smem[];
    __half* sA = (__half*)smem;                  // 64 x AST halfs
    float* sV0 = smem + 12544;
    float* sV1 = smem + 27904;
    float* sL  = smem + 43264;

    const int tid  = threadIdx.x;
    const int lane = tid & 31;
    const int wrp  = tid >> 5;
    const int b    = blockIdx.x / (NS / TSR);
    const int s0   = (blockIdx.x % (NS / TSR)) * TSR;

    const int lm_row = lane & 15;
    const int lm_col = (lane >> 4) * 8;

    const float* vb = v + (size_t)b * NS * ND;

    // ---- P0: prefetch BOTH conv v windows (two cp.async groups) ----
    {
        const unsigned sv0_base = smem_u32(sV0);
        const unsigned sv1_base = smem_u32(sV1);
        // window 0: rows s0-4 .. s0+35
        #pragma unroll
        for (int i = tid; i < VR * (ND / 4); i += NTH) {
            int rr = i / (ND / 4);
            int cc = i % (ND / 4);
            int gr = s0 - NPAD + rr;
            int ok = (gr >= 0 && gr < NS) ? 16 : 0;
            const float4* src = (const float4*)(vb + (size_t)max(gr, 0) * ND) + cc;
            cp_async16(sv0_base + i * 16, src, ok);
        }
        cp_async_commit();
        // window 1: rows s0+28 .. s0+67
        #pragma unroll
        for (int i = tid; i < VR * (ND / 4); i += NTH) {
            int rr = i / (ND / 4);
            int cc = i % (ND / 4);
            int gr = s0 - NPAD + 32 + rr;
            int ok = (gr >= 0 && gr < NS) ? 16 : 0;
            const float4* src = (const float4*)(vb + (size_t)max(gr, 0) * ND) + cc;
            cp_async16(sv1_base + i * 16, src, ok);
        }
        cp_async_commit();
    }

    // ---- P1: sA = fp16(q * ks) ----
    {
        const float4* qb = (const float4*)(q  + ((size_t)b * NS + s0) * ND);
        const float4* kb = (const float4*)(ks + ((size_t)b * NS + s0) * ND);
        #pragma unroll
        for (int i = tid; i < TSR * (ND / 4); i += NTH) {
            int r  = i / (ND / 4);
            int c4 = (i % (ND / 4)) * 4;
            float4 qq = qb[i], kk = kb[i];
            __half2 h01 = __floats2half2_rn(qq.x * kk.x, qq.y * kk.y);
            __half2 h23 = __floats2half2_rn(qq.z * kk.z, qq.w * kk.w);
            uint2 wh;
            wh.x = *reinterpret_cast<unsigned*>(&h01);
            wh.y = *reinterpret_cast<unsigned*>(&h23);
            *(uint2*)&sA[r * AST + c4] = wh;
        }
    }
    __syncthreads();

    // ---- P2: logits[64 x 64] via fp16 mma + ldmatrix ----
    {
        const int wm = wrp & 1;
        const int wn = wrp >> 1;
        const int rq = lane >> 2;
        const int kc = (lane & 3) * 2;
        float acc[2][4];
        #pragma unroll
        for (int mt = 0; mt < 2; mt++)
            #pragma unroll
            for (int p = 0; p < 4; p++) acc[mt][p] = 0.f;

        unsigned a_base[2];
        #pragma unroll
        for (int mt = 0; mt < 2; mt++) {
            int r = wm * 32 + mt * 16 + lm_row;
            a_base[mt] = smem_u32(sA + (size_t)r * AST + lm_col);
        }

        for (int t = 0; t < NKSTEP; t++) {
            uint2 B = *(const uint2*)(g_WkPack + (((size_t)(t * 32 + lane)) * 8 + wn) * 2);
            #pragma unroll
            for (int mt = 0; mt < 2; mt++) {
                unsigned a0, a1, a2, a3;
                ldsm_x4(a0, a1, a2, a3, a_base[mt] + t * 32);
                mma_f16(acc[mt], a0, a1, a2, a3, B.x, B.y);
            }
        }

        int oc = wn * 8 + kc;
        float bk0 = (oc < NKH)     ? bk[oc]     : 0.f;
        float bk1 = (oc + 1 < NKH) ? bk[oc + 1] : 0.f;
        #pragma unroll
        for (int mt = 0; mt < 2; mt++) {
            int r = wm * 32 + mt * 16 + rq;
            sL[r * NKHP + oc]           = acc[mt][0] + bk0;
            sL[r * NKHP + oc + 1]       = acc[mt][1] + bk1;
            sL[(r + 8) * NKHP + oc]     = acc[mt][2] + bk0;
            sL[(r + 8) * NKHP + oc + 1] = acc[mt][3] + bk1;
        }
    }
    __syncthreads();

    // ---- P3: softmax over K=9 taps per (row, head) ----
    if (tid < TSR * NH) {
        int r = tid / NH, h = tid % NH;
        float* p = sL + r * NKHP + h * NK;
        float m = p[0];
        #pragma unroll
        for (int k = 1; k < NK; k++) m = fmaxf(m, p[k]);
        float e[NK], ssum = 0.f;
        #pragma unroll
        for (int k = 0; k < NK; k++) { e[k] = __expf(p[k] - m); ssum += e[k]; }
        float inv = 1.0f / ssum;
        #pragma unroll
        for (int k = 0; k < NK; k++) p[k] = e[k] * inv;
    }
    cp_async_wait<1>();          // window 0 resident (this thread)
    __syncthreads();             // all threads' window-0 copies visible

    // ---- P4: conv, warp-unit = (head, 8-row block); double-buffered v ----
    {
        #pragma unroll
        for (int half = 0; half < 2; half++) {
            const float* sV = (half == 0) ? sV0 : sV1;
            if (half == 1) {
                cp_async_wait<0>();   // window 1 resident
                __syncthreads();      // visibility (single barrier)
            }

            #pragma unroll
            for (int it = 0; it < 2; it++) {
                int uid = wrp + 16 * it;
                if (uid < 24) {
                    int h  = uid % NH;
                    int rb = uid / NH;
                    int c0 = h * NHD + lane * 2;
                    int r0 = rb * 8;

                    float2 w[16];
                    #pragma unroll
                    for (int j = 0; j < 16; j++)
                        w[j] = *(const float2*)&sV[(r0 + j) * ND + c0];

                    #pragma unroll
                    for (int i = 0; i < 8; i++) {
                        int r = half * 32 + r0 + i;
                        const float* dkp = sL + r * NKHP + h * NK;
                        float a0 = 0.f, a1 = 0.f;
                        #pragma unroll
                        for (int k = 0; k < NK; k++) {
                            float dk = dkp[k];
                            a0 = fmaf(dk, w[i + k].x, a0);
                            a1 = fmaf(dk, w[i + k].y, a1);
                        }
                        __half2 hv = __floats2half2_rn(a0, a1);
                        *(unsigned*)&sA[r * AST + c0] = *reinterpret_cast<unsigned*>(&hv);
                    }
                }
            }
        }
        __syncthreads();
    }

    // ---- P5: out[64 x 384] = A @ Wp^T + bp (fp16 mma, A via ldmatrix) ----
    {
        const int warp_m = wrp & 1;
        const int warp_n = wrp >> 1;
        const int rb     = warp_m * 32;
        const int rq     = lane >> 2;
        const int kc     = (lane & 3) * 2;

        float acc[2][NJT][4];
        #pragma unroll
        for (int mt = 0; mt < 2; mt++)
            #pragma unroll
            for (int j = 0; j < NJT; j++)
                #pragma unroll
                for (int p = 0; p < 4; p++) acc[mt][j][p] = 0.f;

        unsigned a_base[2];
        #pragma unroll
        for (int mt = 0; mt < 2; mt++) {
            int r = rb + mt * 16 + lm_row;
            a_base[mt] = smem_u32(sA + (size_t)r * AST + lm_col);
        }

        for (int t = 0; t < NKSTEP; t++) {
            unsigned a[2][4];
            #pragma unroll
            for (int mt = 0; mt < 2; mt++)
                ldsm_x4(a[mt][0], a[mt][1], a[mt][2], a[mt][3], a_base[mt] + t * 32);

            const uint4* bptr =
                (const uint4*)(g_Bpack + ((size_t)((t * NCB + warp_n) * 32 + lane)) * (NJT * 2));
            uint4 B0 = bptr[0], B1 = bptr[1], B2 = bptr[2];
            const unsigned bw[NJT][2] = {
                {B0.x, B0.y}, {B0.z, B0.w},
                {B1.x, B1.y}, {B1.z, B1.w},
                {B2.x, B2.y}, {B2.z, B2.w}};
            #pragma unroll
            for (int j = 0; j < NJT; j++) {
                #pragma unroll
                for (int mt = 0; mt < 2; mt++)
                    mma_f16(acc[mt][j], a[mt][0], a[mt][1], a[mt][2], a[mt][3], bw[j][0], bw[j][1]);
            }
        }

        const int nbase = warp_n * 48;
        float* ob = out + ((size_t)b * NS + s0) * NOUT;
        #pragma unroll
        for (int j = 0; j < NJT; j++) {
            int c = nbase + j * 8 + kc;
            float2 bb = *(const float2*)&bp[c];
            #pragma unroll
            for (int mt = 0; mt < 2; mt++) {
                size_t R = (size_t)(rb + mt * 16 + rq);
                float2 lo = make_float2(acc[mt][j][0] + bb.x, acc[mt][j][1] + bb.y);
                float2 hi = make_float2(acc[mt][j][2] + bb.x, acc[mt][j][3] + bb.y);
                *(float2*)&ob[R * NOUT + c]       = lo;
                *(float2*)&ob[(R + 8) * NOUT + c] = hi;
            }
        }
    }
}

extern "C" void kernel_launch(void* const* d_in, const int* in_sizes, int n_in,
                              void* d_out, int out_size) {
    const float* q  = (const float*)d_in[0];
    const float* ks = (const float*)d_in[1];
    const float* v  = (const float*)d_in[2];
    const float* Wk = (const float*)d_in[3];
    const float* bk = (const float*)d_in[4];
    const float* Wp = (const float*)d_in[5];
    const float* bp = (const float*)d_in[6];
    float* out = (float*)d_out;

    (void)in_sizes; (void)n_in; (void)out_size;

    prep_kernel<<<(BPACK_WORDS + 255) / 256, 256>>>(Wp, Wk);

    const int smem_bytes = SMEM_FLOATS * (int)sizeof(float);  // 189440
    cudaFuncSetAttribute(sdca_fused, cudaFuncAttributeMaxDynamicSharedMemorySize, smem_bytes);
    sdca_fused<<<NB * (NS / TSR), NTH, smem_bytes>>>(q, ks, v, bk, bp, out);
}